// round 12
// baseline (speedup 1.0000x reference)
#include <cuda_runtime.h>
#include <cuda_bf16.h>

#define FULL 0xffffffffu
#define L2E  1.4426950408889634f
#define LN2  0.6931471805599453f
#define CRF_S 1024
#define CRF_T 16
#define ONEBF 0x3F803F80u

static __device__ __forceinline__ float ex2f_(float x){ float y; asm("ex2.approx.ftz.f32 %0,%1;" :"=f"(y):"f"(x)); return y; }
static __device__ __forceinline__ float lg2f_(float x){ float y; asm("lg2.approx.ftz.f32 %0,%1;" :"=f"(y):"f"(x)); return y; }

union UBF { unsigned u; __nv_bfloat162 b; float f; };
static __device__ __forceinline__ unsigned bf2u(__nv_bfloat162 v){ UBF c; c.b = v; return c.u; }
static __device__ __forceinline__ __nv_bfloat162 u2bf(unsigned u){ UBF c; c.u = u; return c.b; }
static __device__ __forceinline__ float bflo_f(unsigned u){ UBF c; c.u = u << 16; return c.f; }
static __device__ __forceinline__ float bfhi_f(unsigned u){ UBF c; c.u = u & 0xffff0000u; return c.f; }

// half-duplication via intrinsics -> HFMA2 half-lane source selectors
#define DLO(x) __low2bfloat162(u2bf(x))
#define DHI(x) __high2bfloat162(u2bf(x))

__device__ float g_nll[1024];

// one recurrence step for one chain (parameterized state), 8-lane group
#define STEP_CORE(PK, GPK, EP, K) \
    unsigned v_ = bf2u(__hmul2(u2bf(PK), u2bf(GPK[(K)]))); \
    unsigned s0=__shfl_sync(FULL,v_,0,8), s1=__shfl_sync(FULL,v_,1,8), \
             s2=__shfl_sync(FULL,v_,2,8), s3=__shfl_sync(FULL,v_,3,8), \
             s4=__shfl_sync(FULL,v_,4,8), s5=__shfl_sync(FULL,v_,5,8), \
             s6=__shfl_sync(FULL,v_,6,8), s7=__shfl_sync(FULL,v_,7,8); \
    __nv_bfloat162 A_ = __hmul2(DLO(s0), EP[0]); \
    __nv_bfloat162 B_ = __hmul2(DHI(s0), EP[1]); \
    __nv_bfloat162 C_ = __hmul2(DLO(s1), EP[2]); \
    __nv_bfloat162 D_ = __hmul2(DHI(s1), EP[3]); \
    A_ = __hfma2(DLO(s2), EP[ 4], A_); \
    B_ = __hfma2(DHI(s2), EP[ 5], B_); \
    C_ = __hfma2(DLO(s3), EP[ 6], C_); \
    D_ = __hfma2(DHI(s3), EP[ 7], D_); \
    A_ = __hfma2(DLO(s4), EP[ 8], A_); \
    B_ = __hfma2(DHI(s4), EP[ 9], B_); \
    C_ = __hfma2(DLO(s5), EP[10], C_); \
    D_ = __hfma2(DHI(s5), EP[11], D_); \
    A_ = __hfma2(DLO(s6), EP[12], A_); \
    B_ = __hfma2(DHI(s6), EP[13], B_); \
    C_ = __hfma2(DLO(s7), EP[14], C_); \
    D_ = __hfma2(DHI(s7), EP[15], D_); \
    A_ = __hadd2(A_, B_); C_ = __hadd2(C_, D_); A_ = __hadd2(A_, C_);

#define RENORMX(PK, PT, OFF) do { \
    unsigned u0_ = __shfl_sync(FULL, PK, 0, 8); \
    int Eb_ = (int)((u0_ >> 7) & 0xffu); \
    unsigned h_ = ((unsigned)(254 - Eb_)) << 7; \
    unsigned scl_ = h_ | (h_ << 16); \
    PK = bf2u(__hmul2(u2bf(PK), u2bf(scl_))); \
    PT = bf2u(__hmul2(u2bf(PT), u2bf(scl_))); \
    OFF += (float)(Eb_ - 127); \
} while (0)

#define STEP_FX(PK, PT, OFF, GPK, EP, K) do { \
    STEP_CORE(PK, GPK, EP, K); \
    PT = v_; PK = bf2u(A_); \
    if (((K)&7)==7) RENORMX(PK, PT, OFF); } while (0)

#define STEP_SX(PK, PT, OFF, GPK, EP, K, GREG, GK) do { \
    STEP_CORE(PK, GPK, EP, K); \
    int g_ = __shfl_sync(FULL, (GREG), (GK), 8); \
    if (g_) { PT = v_; PK = bf2u(A_); } \
    if (((K)&7)==7) RENORMX(PK, PT, OFF); } while (0)

__global__ void __launch_bounds__(64)
crf_forward_kernel(const float* __restrict__ em,
                   const int* __restrict__ tags,
                   const int* __restrict__ mask,
                   const float* __restrict__ trans,
                   const float* __restrict__ start_t,
                   const float* __restrict__ end_t)
{
    __shared__ float s_trans[256];
    __shared__ float s_start[16];
    int tid = threadIdx.x;
    for (int i = tid; i < 256; i += 64) s_trans[i] = trans[i];
    if (tid < 16) s_start[tid] = start_t[tid];
    __syncthreads();

    const int lane = tid & 31;
    const int j8   = lane & 7;                       // lane within 8-lane group
    const int g    = lane >> 3;                      // group 0..3
    const int b    = blockIdx.x * 8 + (tid >> 5) * 4 + g;
    const int c0   = j8 * 2;                         // owned state pair

    const float* emb = em   + (size_t)b * CRF_S * CRF_T;
    const int*   tp  = tags + (size_t)b * CRF_S;
    const int*   mp  = mask + (size_t)b * CRF_S;
    const float* emL = emb + c0;

    // E operands: fwd = column pair, bwd = row pair
    __nv_bfloat162 EpF[16], EpB[16];
    #pragma unroll
    for (int i = 0; i < 16; i++) {
        EpF[i] = __floats2bfloat162_rn(ex2f_(__ldg(trans + i*16 + c0)     * L2E),
                                       ex2f_(__ldg(trans + i*16 + c0 + 1) * L2E));
        EpB[i] = __floats2bfloat162_rn(ex2f_(__ldg(trans + c0*16 + i)     * L2E),
                                       ex2f_(__ldg(trans + (c0+1)*16 + i) * L2E));
    }

    // ---- block-0 preloads, both chains ----
    float2 emF[16], emB[16];
    #pragma unroll
    for (int u = 0; u < 16; u++) {
        emF[u] = __ldg((const float2*)(emL + (size_t)u * 16));
        emB[u] = __ldg((const float2*)(emL + (size_t)(1023 - u) * 16));
    }
    // gold tag/mask/em pipelines, two halves ([0,512) and [512,1024), both ascending)
    int ftA_c = __ldg(tp + j8),        ftB_c = __ldg(tp + 8 + j8);
    int ftA_n = __ldg(tp + 16 + j8),   ftB_n = __ldg(tp + 24 + j8);
    int btA_c = __ldg(tp + 512 + j8),  btB_c = __ldg(tp + 520 + j8);
    int btA_n = __ldg(tp + 528 + j8),  btB_n = __ldg(tp + 536 + j8);
    int fmA_c = __ldg(mp + j8),        fmB_c = __ldg(mp + 8 + j8);
    int bmA_c = __ldg(mp + 512 + j8),  bmB_c = __ldg(mp + 520 + j8);
    int gF0_c = __ldg(mp + j8),        gF1_c = __ldg(mp + 8 + j8);
    int gB0_c = __ldg(mp + 1023 - j8), gB1_c = __ldg(mp + 1015 - j8);
    float feA_c = __ldg(emb + (size_t)(j8)*16       + ftA_c);
    float feB_c = __ldg(emb + (size_t)(8 + j8)*16   + ftB_c);
    float beA_c = __ldg(emb + (size_t)(512 + j8)*16 + btA_c);
    float beB_c = __ldg(emb + (size_t)(520 + j8)*16 + btB_c);

    unsigned pkF, ptF = ONEBF, pkB, ptB = ONEBF;
    float offF, offB = 0.0f, gold = 0.0f;
    int carryF = 0, carryB = __ldg(tp + 511);
    int packlm = -2147483647;

    // ---- init (uniform across warp) ----
    {
        float sA = (s_start[c0]   + emF[0].x) * L2E;
        float sB = (s_start[c0+1] + emF[0].y) * L2E;
        float m0 = __shfl_sync(FULL, sA, 0, 8);
        pkF  = bf2u(__floats2bfloat162_rn(ex2f_(sA - m0), ex2f_(sB - m0)));
        offF = m0;
        pkB  = bf2u(__floats2bfloat162_rn(ex2f_(__ldg(end_t + c0)   * L2E),
                                          ex2f_(__ldg(end_t + c0+1) * L2E)));
        if (j8 == 0) gF0_c = 1;                     // t=0 init ungated per reference
    }

    // ---- gpk for block 0 ----
    unsigned gpkF[16], gpkB[16];
    #pragma unroll
    for (int u = 0; u < 16; u++) {
        gpkF[u] = bf2u(__floats2bfloat162_rn(ex2f_(emF[u].x * L2E), ex2f_(emF[u].y * L2E)));
        gpkB[u] = bf2u(__floats2bfloat162_rn(ex2f_(emB[u].x * L2E), ex2f_(emB[u].y * L2E)));
    }
    gpkF[0] = ONEBF;                                 // em_0 folded into p0

    int ftA_nn = 0, ftB_nn = 0, btA_nn = 0, btB_nn = 0;
    int fmA_n, fmB_n, bmA_n, bmB_n, gF0_n, gF1_n, gB0_n, gB1_n;
    float feA_n, feB_n, beA_n, beB_n;

    for (int nb = 0; nb < 32; nb++) {
        const int k0 = nb * 16;

        // ---- prefetch next block, both chains ----
        if (nb < 31) {
            const int kn = k0 + 16;
            #pragma unroll
            for (int u = 0; u < 16; u++) {
                emF[u] = __ldg((const float2*)(emL + (size_t)(kn + u) * 16));
                emB[u] = __ldg((const float2*)(emL + (size_t)(1023 - kn - u) * 16));
            }
            fmA_n = __ldg(mp + kn + j8);        fmB_n = __ldg(mp + kn + 8 + j8);
            bmA_n = __ldg(mp + 512 + kn + j8);  bmB_n = __ldg(mp + 512 + kn + 8 + j8);
            gF0_n = __ldg(mp + kn + j8);        gF1_n = __ldg(mp + kn + 8 + j8);
            gB0_n = __ldg(mp + 1023 - kn - j8); gB1_n = __ldg(mp + 1015 - kn - j8);
            feA_n = __ldg(emb + (size_t)(kn + j8)*16           + ftA_n);
            feB_n = __ldg(emb + (size_t)(kn + 8 + j8)*16       + ftB_n);
            beA_n = __ldg(emb + (size_t)(512 + kn + j8)*16     + btA_n);
            beB_n = __ldg(emb + (size_t)(512 + kn + 8 + j8)*16 + btB_n);
            if (nb < 30) {
                ftA_nn = __ldg(tp + kn + 16 + j8);       ftB_nn = __ldg(tp + kn + 24 + j8);
                btA_nn = __ldg(tp + 512 + kn + 16 + j8); btB_nn = __ldg(tp + 512 + kn + 24 + j8);
            }
        }

        // ---- gold: 4 lane-local timesteps (fwd half A/B, bwd half A/B) ----
        {
            int t  = k0 + j8;
            int tgp = __shfl_up_sync(FULL, ftA_c, 1, 8);
            int l7  = __shfl_sync(FULL, ftA_c, 7, 8);
            if (j8 == 0) tgp = carryF;
            carryF = l7;
            if (t == 0) {
                gold += s_start[ftA_c] + feA_c;
                if (fmA_c) packlm = ftA_c;
            } else if (fmA_c) {
                gold += feA_c + s_trans[ftA_c*16 + tgp];
                packlm = (t << 4) | ftA_c;
            }
            t   = k0 + 8 + j8;
            tgp = __shfl_up_sync(FULL, ftB_c, 1, 8);
            l7  = __shfl_sync(FULL, ftB_c, 7, 8);
            if (j8 == 0) tgp = carryF;
            carryF = l7;
            if (fmB_c) {
                gold += feB_c + s_trans[ftB_c*16 + tgp];
                packlm = (t << 4) | ftB_c;
            }
            t   = 512 + k0 + j8;
            tgp = __shfl_up_sync(FULL, btA_c, 1, 8);
            l7  = __shfl_sync(FULL, btA_c, 7, 8);
            if (j8 == 0) tgp = carryB;
            carryB = l7;
            if (bmA_c) {
                gold += beA_c + s_trans[btA_c*16 + tgp];
                packlm = (t << 4) | btA_c;
            }
            t   = 512 + k0 + 8 + j8;
            tgp = __shfl_up_sync(FULL, btB_c, 1, 8);
            l7  = __shfl_sync(FULL, btB_c, 7, 8);
            if (j8 == 0) tgp = carryB;
            carryB = l7;
            if (bmB_c) {
                gold += beB_c + s_trans[btB_c*16 + tgp];
                packlm = (t << 4) | btB_c;
            }
        }

        // ---- 16 interleaved rounds (F step + B step), warp-uniform dispatch ----
        const unsigned bal = __ballot_sync(FULL,
            (gF0_c != 0) && (gF1_c != 0) && (gB0_c != 0) && (gB1_c != 0));
        if (bal == FULL) {
            STEP_FX(pkF, ptF, offF, gpkF, EpF, 0);  STEP_FX(pkB, ptB, offB, gpkB, EpB, 0);
            STEP_FX(pkF, ptF, offF, gpkF, EpF, 1);  STEP_FX(pkB, ptB, offB, gpkB, EpB, 1);
            STEP_FX(pkF, ptF, offF, gpkF, EpF, 2);  STEP_FX(pkB, ptB, offB, gpkB, EpB, 2);
            STEP_FX(pkF, ptF, offF, gpkF, EpF, 3);  STEP_FX(pkB, ptB, offB, gpkB, EpB, 3);
            STEP_FX(pkF, ptF, offF, gpkF, EpF, 4);  STEP_FX(pkB, ptB, offB, gpkB, EpB, 4);
            STEP_FX(pkF, ptF, offF, gpkF, EpF, 5);  STEP_FX(pkB, ptB, offB, gpkB, EpB, 5);
            STEP_FX(pkF, ptF, offF, gpkF, EpF, 6);  STEP_FX(pkB, ptB, offB, gpkB, EpB, 6);
            STEP_FX(pkF, ptF, offF, gpkF, EpF, 7);  STEP_FX(pkB, ptB, offB, gpkB, EpB, 7);
            STEP_FX(pkF, ptF, offF, gpkF, EpF, 8);  STEP_FX(pkB, ptB, offB, gpkB, EpB, 8);
            STEP_FX(pkF, ptF, offF, gpkF, EpF, 9);  STEP_FX(pkB, ptB, offB, gpkB, EpB, 9);
            STEP_FX(pkF, ptF, offF, gpkF, EpF, 10); STEP_FX(pkB, ptB, offB, gpkB, EpB, 10);
            STEP_FX(pkF, ptF, offF, gpkF, EpF, 11); STEP_FX(pkB, ptB, offB, gpkB, EpB, 11);
            STEP_FX(pkF, ptF, offF, gpkF, EpF, 12); STEP_FX(pkB, ptB, offB, gpkB, EpB, 12);
            STEP_FX(pkF, ptF, offF, gpkF, EpF, 13); STEP_FX(pkB, ptB, offB, gpkB, EpB, 13);
            STEP_FX(pkF, ptF, offF, gpkF, EpF, 14); STEP_FX(pkB, ptB, offB, gpkB, EpB, 14);
            STEP_FX(pkF, ptF, offF, gpkF, EpF, 15); STEP_FX(pkB, ptB, offB, gpkB, EpB, 15);
        } else {
            STEP_SX(pkF, ptF, offF, gpkF, EpF, 0,  gF0_c, 0); STEP_SX(pkB, ptB, offB, gpkB, EpB, 0,  gB0_c, 0);
            STEP_SX(pkF, ptF, offF, gpkF, EpF, 1,  gF0_c, 1); STEP_SX(pkB, ptB, offB, gpkB, EpB, 1,  gB0_c, 1);
            STEP_SX(pkF, ptF, offF, gpkF, EpF, 2,  gF0_c, 2); STEP_SX(pkB, ptB, offB, gpkB, EpB, 2,  gB0_c, 2);
            STEP_SX(pkF, ptF, offF, gpkF, EpF, 3,  gF0_c, 3); STEP_SX(pkB, ptB, offB, gpkB, EpB, 3,  gB0_c, 3);
            STEP_SX(pkF, ptF, offF, gpkF, EpF, 4,  gF0_c, 4); STEP_SX(pkB, ptB, offB, gpkB, EpB, 4,  gB0_c, 4);
            STEP_SX(pkF, ptF, offF, gpkF, EpF, 5,  gF0_c, 5); STEP_SX(pkB, ptB, offB, gpkB, EpB, 5,  gB0_c, 5);
            STEP_SX(pkF, ptF, offF, gpkF, EpF, 6,  gF0_c, 6); STEP_SX(pkB, ptB, offB, gpkB, EpB, 6,  gB0_c, 6);
            STEP_SX(pkF, ptF, offF, gpkF, EpF, 7,  gF0_c, 7); STEP_SX(pkB, ptB, offB, gpkB, EpB, 7,  gB0_c, 7);
            STEP_SX(pkF, ptF, offF, gpkF, EpF, 8,  gF1_c, 0); STEP_SX(pkB, ptB, offB, gpkB, EpB, 8,  gB1_c, 0);
            STEP_SX(pkF, ptF, offF, gpkF, EpF, 9,  gF1_c, 1); STEP_SX(pkB, ptB, offB, gpkB, EpB, 9,  gB1_c, 1);
            STEP_SX(pkF, ptF, offF, gpkF, EpF, 10, gF1_c, 2); STEP_SX(pkB, ptB, offB, gpkB, EpB, 10, gB1_c, 2);
            STEP_SX(pkF, ptF, offF, gpkF, EpF, 11, gF1_c, 3); STEP_SX(pkB, ptB, offB, gpkB, EpB, 11, gB1_c, 3);
            STEP_SX(pkF, ptF, offF, gpkF, EpF, 12, gF1_c, 4); STEP_SX(pkB, ptB, offB, gpkB, EpB, 12, gB1_c, 4);
            STEP_SX(pkF, ptF, offF, gpkF, EpF, 13, gF1_c, 5); STEP_SX(pkB, ptB, offB, gpkB, EpB, 13, gB1_c, 5);
            STEP_SX(pkF, ptF, offF, gpkF, EpF, 14, gF1_c, 6); STEP_SX(pkB, ptB, offB, gpkB, EpB, 14, gB1_c, 6);
            STEP_SX(pkF, ptF, offF, gpkF, EpF, 15, gF1_c, 7); STEP_SX(pkB, ptB, offB, gpkB, EpB, 15, gB1_c, 7);
        }

        // ---- convert prefetched -> gpk; rotate pipelines ----
        if (nb < 31) {
            #pragma unroll
            for (int u = 0; u < 16; u++) {
                gpkF[u] = bf2u(__floats2bfloat162_rn(ex2f_(emF[u].x * L2E), ex2f_(emF[u].y * L2E)));
                gpkB[u] = bf2u(__floats2bfloat162_rn(ex2f_(emB[u].x * L2E), ex2f_(emB[u].y * L2E)));
            }
            ftA_c = ftA_n; ftB_c = ftB_n; ftA_n = ftA_nn; ftB_n = ftB_nn;
            btA_c = btA_n; btB_c = btB_n; btA_n = btA_nn; btB_n = btB_nn;
            fmA_c = fmA_n; fmB_c = fmB_n; bmA_c = bmA_n; bmB_c = bmB_n;
            gF0_c = gF0_n; gF1_c = gF1_n; gB0_c = gB0_n; gB1_c = gB1_n;
            feA_c = feA_n; feB_c = feB_n; beA_c = beA_n; beB_c = beB_n;
        }
    }

    // ---- epilogue: Z = sum_s alpha_511(s) * beta_511(s), all in-lane ----
    float z = bflo_f(ptF)*bflo_f(pkB) + bfhi_f(ptF)*bfhi_f(pkB);
    z += __shfl_xor_sync(FULL, z, 4, 8);
    z += __shfl_xor_sync(FULL, z, 2, 8);
    z += __shfl_xor_sync(FULL, z, 1, 8);

    gold += __shfl_xor_sync(FULL, gold, 4, 8);
    gold += __shfl_xor_sync(FULL, gold, 2, 8);
    gold += __shfl_xor_sync(FULL, gold, 1, 8);

    packlm = max(packlm, __shfl_xor_sync(FULL, packlm, 4, 8));
    packlm = max(packlm, __shfl_xor_sync(FULL, packlm, 2, 8));
    packlm = max(packlm, __shfl_xor_sync(FULL, packlm, 1, 8));

    if (j8 == 0) {
        const int ltf = packlm & 15;
        const float logZ = (offF + offB + lg2f_(z)) * LN2;
        g_nll[b] = logZ - (gold + __ldg(end_t + ltf));
    }
}

__global__ void crf_reduce_kernel(float* __restrict__ out)
{
    __shared__ float sm[256];
    int tid = threadIdx.x;
    float v = g_nll[tid] + g_nll[tid + 256] + g_nll[tid + 512] + g_nll[tid + 768];
    sm[tid] = v;
    __syncthreads();
    #pragma unroll
    for (int s = 128; s > 0; s >>= 1) {
        if (tid < s) sm[tid] += sm[tid + s];
        __syncthreads();
    }
    if (tid == 0) out[0] = sm[0] * (1.0f / 1024.0f);
}

extern "C" void kernel_launch(void* const* d_in, const int* in_sizes, int n_in,
                              void* d_out, int out_size)
{
    const float* emissions = (const float*)d_in[0];
    const int*   tags      = (const int*)d_in[1];
    const int*   mask      = (const int*)d_in[2];
    const float* trans     = (const float*)d_in[3];
    const float* start_t   = (const float*)d_in[4];
    const float* end_t     = (const float*)d_in[5];
    float* out = (float*)d_out;

    crf_forward_kernel<<<128, 64>>>(emissions, tags, mask, trans, start_t, end_t);
    crf_reduce_kernel<<<1, 256>>>(out);
}

// round 13
// speedup vs baseline: 1.1718x; 1.1718x over previous
#include <cuda_runtime.h>
#include <cuda_bf16.h>

#define FULL 0xffffffffu
#define L2E  1.4426950408889634f
#define LN2  0.6931471805599453f
#define CRF_S 1024
#define CRF_T 16
#define ONEBF 0x3F803F80u

static __device__ __forceinline__ float ex2f_(float x){ float y; asm("ex2.approx.ftz.f32 %0,%1;" :"=f"(y):"f"(x)); return y; }
static __device__ __forceinline__ float lg2f_(float x){ float y; asm("lg2.approx.ftz.f32 %0,%1;" :"=f"(y):"f"(x)); return y; }

union UBF { unsigned u; __nv_bfloat162 b; float f; };
static __device__ __forceinline__ unsigned bf2u(__nv_bfloat162 v){ UBF c; c.b = v; return c.u; }
static __device__ __forceinline__ __nv_bfloat162 u2bf(unsigned u){ UBF c; c.u = u; return c.b; }
static __device__ __forceinline__ float bflo_f(unsigned u){ UBF c; c.u = u << 16; return c.f; }
static __device__ __forceinline__ float bfhi_f(unsigned u){ UBF c; c.u = u & 0xffff0000u; return c.f; }

// half-duplication via intrinsics -> HFMA2 half-lane source selectors (no PRMT)
#define DLO(x) __low2bfloat162(u2bf(x))
#define DHI(x) __high2bfloat162(u2bf(x))

__device__ float g_nll[1024];

// gather + 16x2 FMA tree within an 8-lane group; lane k holds packed (v_2k, v_2k+1)
#define GATHER_TREE \
    unsigned s0=__shfl_sync(FULL,v_,0,8), s1=__shfl_sync(FULL,v_,1,8), \
             s2=__shfl_sync(FULL,v_,2,8), s3=__shfl_sync(FULL,v_,3,8), \
             s4=__shfl_sync(FULL,v_,4,8), s5=__shfl_sync(FULL,v_,5,8), \
             s6=__shfl_sync(FULL,v_,6,8), s7=__shfl_sync(FULL,v_,7,8); \
    __nv_bfloat162 A_ = __hmul2(DLO(s0), Ep[0]); \
    __nv_bfloat162 B_ = __hmul2(DHI(s0), Ep[1]); \
    __nv_bfloat162 C_ = __hmul2(DLO(s1), Ep[2]); \
    __nv_bfloat162 D_ = __hmul2(DHI(s1), Ep[3]); \
    A_ = __hfma2(DLO(s2), Ep[ 4], A_); \
    B_ = __hfma2(DHI(s2), Ep[ 5], B_); \
    C_ = __hfma2(DLO(s3), Ep[ 6], C_); \
    D_ = __hfma2(DHI(s3), Ep[ 7], D_); \
    A_ = __hfma2(DLO(s4), Ep[ 8], A_); \
    B_ = __hfma2(DHI(s4), Ep[ 9], B_); \
    C_ = __hfma2(DLO(s5), Ep[10], C_); \
    D_ = __hfma2(DHI(s5), Ep[11], D_); \
    A_ = __hfma2(DLO(s6), Ep[12], A_); \
    B_ = __hfma2(DHI(s6), Ep[13], B_); \
    C_ = __hfma2(DLO(s7), Ep[14], C_); \
    D_ = __hfma2(DHI(s7), Ep[15], D_); \
    A_ = __hadd2(A_, B_); C_ = __hadd2(C_, D_); A_ = __hadd2(A_, C_);

// integer renorm: power-of-2 scale so group-lane-0 low-half ~ 1.0 (exact in bf16)
#define RENORM do { \
    unsigned u0_ = __shfl_sync(FULL, pku, 0, 8); \
    int Eb_ = (int)((u0_ >> 7) & 0xffu); \
    unsigned h_ = ((unsigned)(254 - Eb_)) << 7; \
    unsigned scl_ = h_ | (h_ << 16); \
    pku  = bf2u(__hmul2(u2bf(pku),  u2bf(scl_))); \
    ptrk = bf2u(__hmul2(u2bf(ptrk), u2bf(scl_))); \
    off2 += (float)(Eb_ - 127); \
} while (0)

#define STEP_F(K) do { \
    unsigned v_ = bf2u(__hmul2(u2bf(pku), u2bf(gpk_c[(K)]))); \
    GATHER_TREE; \
    ptrk = v_; pku = bf2u(A_); \
    if (((K)&7)==7) RENORM; } while (0)

#define STEP_S(K, GREG, GK) do { \
    unsigned v_ = bf2u(__hmul2(u2bf(pku), u2bf(gpk_c[(K)]))); \
    int g_ = __shfl_sync(FULL, (GREG), (GK), 8); \
    GATHER_TREE; \
    if (g_) { ptrk = v_; pku = bf2u(A_); } \
    if (((K)&7)==7) RENORM; } while (0)

__global__ void __launch_bounds__(128, 1)
crf_forward_kernel(const float* __restrict__ em,
                   const int* __restrict__ tags,
                   const int* __restrict__ mask,
                   const float* __restrict__ trans,
                   const float* __restrict__ start_t,
                   const float* __restrict__ end_t)
{
    __shared__ float s_trans[256];
    __shared__ float s_start[16];
    int tid = threadIdx.x;
    for (int i = tid; i < 256; i += 128) s_trans[i] = trans[i];
    if (tid < 16) s_start[tid] = start_t[tid];
    __syncthreads();

    const int  lane  = tid & 31;
    const int  j8    = lane & 7;           // lane within 8-lane group
    const int  g     = lane >> 3;          // group 0..3: {0,2}=fwd, {1,3}=bwd (2,3 mirror 0,1)
    const bool isBwd = (g & 1);
    const int  b     = blockIdx.x * 4 + (tid >> 5);   // ONE batch per warp
    const int  c0    = j8 * 2;             // owned/dest state pair

    const float* emb = em   + (size_t)b * CRF_S * CRF_T;
    const int*   tp  = tags + (size_t)b * CRF_S;
    const int*   mp  = mask + (size_t)b * CRF_S;

    // fwd: Ep[i] = (E[i][c0], E[i][c0+1]);  bwd: Ep[i] = (E[c0][i], E[c0+1][i])
    __nv_bfloat162 Ep[16];
    #pragma unroll
    for (int i = 0; i < 16; i++) {
        int iA = isBwd ? (c0*16 + i)     : (i*16 + c0);
        int iB = isBwd ? ((c0+1)*16 + i) : (i*16 + c0 + 1);
        Ep[i] = __floats2bfloat162_rn(ex2f_(__ldg(trans + iA) * L2E),
                                      ex2f_(__ldg(trans + iB) * L2E));
    }

    const int gateBase = isBwd ? 1023 : 0;     // emission/gate stream
    const int gdir     = isBwd ? -1   : 1;
    const int goldBase = isBwd ? 512  : 0;     // gold stream (ascending)
    const float* emL   = emb + c0;

    // ---- preload: block 0 emissions; tags for blocks 0 and 1; masks/gates block 0;
    //      gold emissions for block 0 ----
    float2 em_buf[16];
    #pragma unroll
    for (int u = 0; u < 16; u++)
        em_buf[u] = __ldg((const float2*)(emL + (size_t)(gateBase + gdir*u) * 16));
    int tagA_c  = __ldg(tp + goldBase + j8);
    int tagB_c  = __ldg(tp + goldBase + 8 + j8);
    int tagA_n  = __ldg(tp + goldBase + 16 + j8);
    int tagB_n  = __ldg(tp + goldBase + 24 + j8);
    int mskA_c  = __ldg(mp + goldBase + j8);
    int mskB_c  = __ldg(mp + goldBase + 8 + j8);
    int gate0_c = __ldg(mp + gateBase + gdir*j8);
    int gate1_c = __ldg(mp + gateBase + gdir*(8 + j8));
    float emgA_c = __ldg(emb + (size_t)(goldBase + j8)*16     + tagA_c);
    float emgB_c = __ldg(emb + (size_t)(goldBase + 8 + j8)*16 + tagB_c);

    unsigned pku, ptrk = ONEBF;
    float off2, gold = 0.0f;
    int carry_tag = isBwd ? __ldg(tp + 511) : 0;
    int packlm = -2147483647;

    // ---- init state (uniform across warp; select after) ----
    {
        float sA = (s_start[c0]   + em_buf[0].x) * L2E;
        float sB = (s_start[c0+1] + em_buf[0].y) * L2E;
        float m0 = __shfl_sync(FULL, sA, 0, 8);
        unsigned pf = bf2u(__floats2bfloat162_rn(ex2f_(sA - m0), ex2f_(sB - m0)));
        unsigned pb = bf2u(__floats2bfloat162_rn(ex2f_(__ldg(end_t + c0)   * L2E),
                                                 ex2f_(__ldg(end_t + c0+1) * L2E)));
        pku  = isBwd ? pb : pf;
        off2 = isBwd ? 0.0f : m0;
        if (!isBwd && j8 == 0) gate0_c = 1;              // t=0 init ungated per reference
    }

    // ---- gpk for block 0 ----
    unsigned gpk_c[16];
    #pragma unroll
    for (int u = 0; u < 16; u++)
        gpk_c[u] = bf2u(__floats2bfloat162_rn(ex2f_(em_buf[u].x * L2E),
                                              ex2f_(em_buf[u].y * L2E)));
    if (!isBwd) gpk_c[0] = ONEBF;                        // em_0 already folded into p0

    int tagA_nn = 0, tagB_nn = 0;
    int mskA_n, mskB_n, gate0_n, gate1_n;
    float emgA_n, emgB_n;

    for (int nb = 0; nb < 32; nb++) {
        const int k0 = nb * 16;

        // ---- prefetch: emissions/masks/gold-em for nb+1 (tags resolved), tags nb+2 ----
        if (nb < 31) {
            const int kn = k0 + 16;
            #pragma unroll
            for (int u = 0; u < 16; u++)
                em_buf[u] = __ldg((const float2*)(emL + (size_t)(gateBase + gdir*(kn + u)) * 16));
            mskA_n  = __ldg(mp + goldBase + kn + j8);
            mskB_n  = __ldg(mp + goldBase + kn + 8 + j8);
            gate0_n = __ldg(mp + gateBase + gdir*(kn + j8));
            gate1_n = __ldg(mp + gateBase + gdir*(kn + 8 + j8));
            emgA_n  = __ldg(emb + (size_t)(goldBase + kn + j8)*16     + tagA_n);
            emgB_n  = __ldg(emb + (size_t)(goldBase + kn + 8 + j8)*16 + tagB_n);
            if (nb < 30) {
                tagA_nn = __ldg(tp + goldBase + kn + 16 + j8);
                tagB_nn = __ldg(tp + goldBase + kn + 24 + j8);
            }
        }

        // ---- gold path: 2 timesteps per lane per block (mirrored in groups 2,3) ----
        {
            int t  = goldBase + k0 + j8;
            int tgp = __shfl_up_sync(FULL, tagA_c, 1, 8);
            int l7  = __shfl_sync(FULL, tagA_c, 7, 8);
            if (j8 == 0) tgp = carry_tag;
            carry_tag = l7;
            if (t == 0) {
                gold += s_start[tagA_c] + emgA_c;
                if (mskA_c) packlm = tagA_c;
            } else if (mskA_c) {
                gold += emgA_c + s_trans[tagA_c*16 + tgp];
                packlm = (t << 4) | tagA_c;
            }
            t   = goldBase + k0 + 8 + j8;
            tgp = __shfl_up_sync(FULL, tagB_c, 1, 8);
            l7  = __shfl_sync(FULL, tagB_c, 7, 8);
            if (j8 == 0) tgp = carry_tag;
            carry_tag = l7;
            if (mskB_c) {
                gold += emgB_c + s_trans[tagB_c*16 + tgp];
                packlm = (t << 4) | tagB_c;
            }
        }

        // ---- 16 recurrence steps (warp-uniform dispatch) ----
        const unsigned bal = __ballot_sync(FULL, (gate0_c != 0) && (gate1_c != 0));
        if (bal == FULL) {
            STEP_F(0);  STEP_F(1);  STEP_F(2);  STEP_F(3);
            STEP_F(4);  STEP_F(5);  STEP_F(6);  STEP_F(7);
            STEP_F(8);  STEP_F(9);  STEP_F(10); STEP_F(11);
            STEP_F(12); STEP_F(13); STEP_F(14); STEP_F(15);
        } else {
            STEP_S(0,  gate0_c, 0); STEP_S(1,  gate0_c, 1);
            STEP_S(2,  gate0_c, 2); STEP_S(3,  gate0_c, 3);
            STEP_S(4,  gate0_c, 4); STEP_S(5,  gate0_c, 5);
            STEP_S(6,  gate0_c, 6); STEP_S(7,  gate0_c, 7);
            STEP_S(8,  gate1_c, 0); STEP_S(9,  gate1_c, 1);
            STEP_S(10, gate1_c, 2); STEP_S(11, gate1_c, 3);
            STEP_S(12, gate1_c, 4); STEP_S(13, gate1_c, 5);
            STEP_S(14, gate1_c, 6); STEP_S(15, gate1_c, 7);
        }

        // ---- convert prefetched block -> gpk; rotate pipeline ----
        if (nb < 31) {
            #pragma unroll
            for (int u = 0; u < 16; u++)
                gpk_c[u] = bf2u(__floats2bfloat162_rn(ex2f_(em_buf[u].x * L2E),
                                                      ex2f_(em_buf[u].y * L2E)));
            tagA_c = tagA_n; tagB_c = tagB_n;
            tagA_n = tagA_nn; tagB_n = tagB_nn;
            mskA_c = mskA_n; mskB_c = mskB_n;
            gate0_c = gate0_n; gate1_c = gate1_n;
            emgA_c = emgA_n; emgB_c = emgB_n;
        }
    }

    // ---- epilogue: Z = sum_s alpha_511(s) * beta_511(s) ----
    // group0 (fwd) pairs with group1 (bwd); groups 2,3 mirror and are ignored.
    unsigned fin  = isBwd ? pku : ptrk;
    unsigned oth  = __shfl_sync(FULL, fin,  (lane + 8) & 31, 32);
    float    offO = __shfl_sync(FULL, off2, (lane + 8) & 31, 32);

    float z = 0.0f;
    if (!isBwd)
        z = bflo_f(fin)*bflo_f(oth) + bfhi_f(fin)*bfhi_f(oth);
    z += __shfl_xor_sync(FULL, z, 4, 8);
    z += __shfl_xor_sync(FULL, z, 2, 8);
    z += __shfl_xor_sync(FULL, z, 1, 8);

    gold += __shfl_xor_sync(FULL, gold, 4, 8);
    gold += __shfl_xor_sync(FULL, gold, 2, 8);
    gold += __shfl_xor_sync(FULL, gold, 1, 8);
    float goldO = __shfl_sync(FULL, gold, (lane + 8) & 31, 32);

    packlm = max(packlm, __shfl_xor_sync(FULL, packlm, 4, 8));
    packlm = max(packlm, __shfl_xor_sync(FULL, packlm, 2, 8));
    packlm = max(packlm, __shfl_xor_sync(FULL, packlm, 1, 8));
    int pmO = __shfl_sync(FULL, packlm, (lane + 8) & 31, 32);

    if (lane == 0) {
        const int pm  = max(packlm, pmO);
        const int ltf = pm & 15;
        const float logZ = (off2 + offO + lg2f_(z)) * LN2;
        g_nll[b] = logZ - (gold + goldO + __ldg(end_t + ltf));
    }
}

__global__ void crf_reduce_kernel(float* __restrict__ out)
{
    __shared__ float sm[256];
    int tid = threadIdx.x;
    float v = g_nll[tid] + g_nll[tid + 256] + g_nll[tid + 512] + g_nll[tid + 768];
    sm[tid] = v;
    __syncthreads();
    #pragma unroll
    for (int s = 128; s > 0; s >>= 1) {
        if (tid < s) sm[tid] += sm[tid + s];
        __syncthreads();
    }
    if (tid == 0) out[0] = sm[0] * (1.0f / 1024.0f);
}

extern "C" void kernel_launch(void* const* d_in, const int* in_sizes, int n_in,
                              void* d_out, int out_size)
{
    const float* emissions = (const float*)d_in[0];
    const int*   tags      = (const int*)d_in[1];
    const int*   mask      = (const int*)d_in[2];
    const float* trans     = (const float*)d_in[3];
    const float* start_t   = (const float*)d_in[4];
    const float* end_t     = (const float*)d_in[5];
    float* out = (float*)d_out;

    crf_forward_kernel<<<256, 128>>>(emissions, tags, mask, trans, start_t, end_t);
    crf_reduce_kernel<<<1, 256>>>(out);
}

// round 14
// speedup vs baseline: 1.3468x; 1.1494x over previous
#include <cuda_runtime.h>
#include <cuda_bf16.h>

#define FULL 0xffffffffu
#define L2E  1.4426950408889634f
#define LN2  0.6931471805599453f
#define CRF_S 1024
#define CRF_T 16
#define ONEBF 0x3F803F80u

static __device__ __forceinline__ float ex2f_(float x){ float y; asm("ex2.approx.ftz.f32 %0,%1;" :"=f"(y):"f"(x)); return y; }
static __device__ __forceinline__ float lg2f_(float x){ float y; asm("lg2.approx.ftz.f32 %0,%1;" :"=f"(y):"f"(x)); return y; }

union UBF { unsigned u; __nv_bfloat162 b; float f; };
static __device__ __forceinline__ unsigned bf2u(__nv_bfloat162 v){ UBF c; c.b = v; return c.u; }
static __device__ __forceinline__ __nv_bfloat162 u2bf(unsigned u){ UBF c; c.u = u; return c.b; }
static __device__ __forceinline__ float bflo_f(unsigned u){ UBF c; c.u = u << 16; return c.f; }
static __device__ __forceinline__ float bfhi_f(unsigned u){ UBF c; c.u = u & 0xffff0000u; return c.f; }

// half-duplication via intrinsics -> HFMA2 half-lane source selectors (no PRMT)
#define DLO(x) __low2bfloat162(u2bf(x))
#define DHI(x) __high2bfloat162(u2bf(x))

__device__ float g_nll[1024];

// gather + 16x2 FMA tree within an 8-lane group; lane k holds packed (v_2k, v_2k+1)
#define GATHER_TREE \
    unsigned s0=__shfl_sync(FULL,v_,0,8), s1=__shfl_sync(FULL,v_,1,8), \
             s2=__shfl_sync(FULL,v_,2,8), s3=__shfl_sync(FULL,v_,3,8), \
             s4=__shfl_sync(FULL,v_,4,8), s5=__shfl_sync(FULL,v_,5,8), \
             s6=__shfl_sync(FULL,v_,6,8), s7=__shfl_sync(FULL,v_,7,8); \
    __nv_bfloat162 A_ = __hmul2(DLO(s0), Ep[0]); \
    __nv_bfloat162 B_ = __hmul2(DHI(s0), Ep[1]); \
    __nv_bfloat162 C_ = __hmul2(DLO(s1), Ep[2]); \
    __nv_bfloat162 D_ = __hmul2(DHI(s1), Ep[3]); \
    A_ = __hfma2(DLO(s2), Ep[ 4], A_); \
    B_ = __hfma2(DHI(s2), Ep[ 5], B_); \
    C_ = __hfma2(DLO(s3), Ep[ 6], C_); \
    D_ = __hfma2(DHI(s3), Ep[ 7], D_); \
    A_ = __hfma2(DLO(s4), Ep[ 8], A_); \
    B_ = __hfma2(DHI(s4), Ep[ 9], B_); \
    C_ = __hfma2(DLO(s5), Ep[10], C_); \
    D_ = __hfma2(DHI(s5), Ep[11], D_); \
    A_ = __hfma2(DLO(s6), Ep[12], A_); \
    B_ = __hfma2(DHI(s6), Ep[13], B_); \
    C_ = __hfma2(DLO(s7), Ep[14], C_); \
    D_ = __hfma2(DHI(s7), Ep[15], D_); \
    A_ = __hadd2(A_, B_); C_ = __hadd2(C_, D_); A_ = __hadd2(A_, C_);

// OLD renorm (explicit state scaling) — used only in the masked (STEP_S) path
#define RENORM do { \
    unsigned u0_ = __shfl_sync(FULL, pku, 0, 8); \
    int Eb_ = (int)((u0_ >> 7) & 0xffu); \
    unsigned h_ = ((unsigned)(254 - Eb_)) << 7; \
    unsigned scl_ = h_ | (h_ << 16); \
    pku  = bf2u(__hmul2(u2bf(pku),  u2bf(scl_))); \
    ptrk = bf2u(__hmul2(u2bf(ptrk), u2bf(scl_))); \
    off2 += (float)(Eb_ - 127); \
} while (0)

// fast-path step, no renorm
#define STEP_F(K) do { \
    unsigned v_ = bf2u(__hmul2(u2bf(pku), u2bf(gpk_c[(K)]))); \
    GATHER_TREE; \
    ptrk = v_; pku = bf2u(A_); } while (0)

// fast-path step WITH off-chain renorm: scale folded into gpk_c[K+1]
// (s0 low-half exponent known at +26cyc, processed in parallel with the tree;
//  power-of-2 bf16 multiply is exact; off2 tracks it)
#define STEP_FR(K) do { \
    unsigned v_ = bf2u(__hmul2(u2bf(pku), u2bf(gpk_c[(K)]))); \
    GATHER_TREE; \
    ptrk = v_; pku = bf2u(A_); \
    int Eb_ = (int)((s0 >> 7) & 0xffu); \
    unsigned h_ = ((unsigned)(254 - Eb_)) << 7; \
    unsigned scl_ = h_ | (h_ << 16); \
    gpk_c[(K)+1] = bf2u(__hmul2(u2bf(gpk_c[(K)+1]), u2bf(scl_))); \
    off2 += (float)(Eb_ - 127); } while (0)

#define STEP_S(K, GREG, GK) do { \
    unsigned v_ = bf2u(__hmul2(u2bf(pku), u2bf(gpk_c[(K)]))); \
    int g_ = __shfl_sync(FULL, (GREG), (GK), 8); \
    GATHER_TREE; \
    if (g_) { ptrk = v_; pku = bf2u(A_); } \
    if (((K)&7)==7) RENORM; } while (0)

__global__ void __launch_bounds__(128, 1)
crf_forward_kernel(const float* __restrict__ em,
                   const int* __restrict__ tags,
                   const int* __restrict__ mask,
                   const float* __restrict__ trans,
                   const float* __restrict__ start_t,
                   const float* __restrict__ end_t)
{
    __shared__ float s_trans[256];
    __shared__ float s_start[16];
    int tid = threadIdx.x;
    for (int i = tid; i < 256; i += 128) s_trans[i] = trans[i];
    if (tid < 16) s_start[tid] = start_t[tid];
    __syncthreads();

    const int  lane  = tid & 31;
    const int  j8    = lane & 7;           // lane within 8-lane group
    const int  g     = lane >> 3;          // group 0..3
    const bool isBwd = (g & 1);
    const int  b     = blockIdx.x * 8 + (tid >> 5) * 2 + (g >> 1);
    const int  c0    = j8 * 2;             // owned/dest state pair

    const float* emb = em   + (size_t)b * CRF_S * CRF_T;
    const int*   tp  = tags + (size_t)b * CRF_S;
    const int*   mp  = mask + (size_t)b * CRF_S;

    // fwd: Ep[i] = (E[i][c0], E[i][c0+1]);  bwd: Ep[i] = (E[c0][i], E[c0+1][i])
    __nv_bfloat162 Ep[16];
    #pragma unroll
    for (int i = 0; i < 16; i++) {
        int iA = isBwd ? (c0*16 + i)     : (i*16 + c0);
        int iB = isBwd ? ((c0+1)*16 + i) : (i*16 + c0 + 1);
        Ep[i] = __floats2bfloat162_rn(ex2f_(__ldg(trans + iA) * L2E),
                                      ex2f_(__ldg(trans + iB) * L2E));
    }

    const int gateBase = isBwd ? 1023 : 0;     // emission/gate stream
    const int gdir     = isBwd ? -1   : 1;
    const int goldBase = isBwd ? 512  : 0;     // gold stream (ascending)
    const float* emL   = emb + c0;

    // ---- preload: block 0 emissions; tags for blocks 0 and 1; masks/gates block 0;
    //      gold emissions for block 0 ----
    float2 em_buf[16];
    #pragma unroll
    for (int u = 0; u < 16; u++)
        em_buf[u] = __ldg((const float2*)(emL + (size_t)(gateBase + gdir*u) * 16));
    int tagA_c  = __ldg(tp + goldBase + j8);
    int tagB_c  = __ldg(tp + goldBase + 8 + j8);
    int tagA_n  = __ldg(tp + goldBase + 16 + j8);
    int tagB_n  = __ldg(tp + goldBase + 24 + j8);
    int mskA_c  = __ldg(mp + goldBase + j8);
    int mskB_c  = __ldg(mp + goldBase + 8 + j8);
    int gate0_c = __ldg(mp + gateBase + gdir*j8);
    int gate1_c = __ldg(mp + gateBase + gdir*(8 + j8));
    float emgA_c = __ldg(emb + (size_t)(goldBase + j8)*16     + tagA_c);
    float emgB_c = __ldg(emb + (size_t)(goldBase + 8 + j8)*16 + tagB_c);

    unsigned pku, ptrk = ONEBF;
    float off2, gold = 0.0f;
    int carry_tag = isBwd ? __ldg(tp + 511) : 0;
    int packlm = -2147483647;

    // ---- init state (uniform across warp; select after) ----
    {
        float sA = (s_start[c0]   + em_buf[0].x) * L2E;
        float sB = (s_start[c0+1] + em_buf[0].y) * L2E;
        float m0 = __shfl_sync(FULL, sA, 0, 8);
        unsigned pf = bf2u(__floats2bfloat162_rn(ex2f_(sA - m0), ex2f_(sB - m0)));
        unsigned pb = bf2u(__floats2bfloat162_rn(ex2f_(__ldg(end_t + c0)   * L2E),
                                                 ex2f_(__ldg(end_t + c0+1) * L2E)));
        pku  = isBwd ? pb : pf;
        off2 = isBwd ? 0.0f : m0;
        if (!isBwd && j8 == 0) gate0_c = 1;              // t=0 init ungated per reference
    }

    // ---- gpk for block 0 ----
    unsigned gpk_c[16];
    #pragma unroll
    for (int u = 0; u < 16; u++)
        gpk_c[u] = bf2u(__floats2bfloat162_rn(ex2f_(em_buf[u].x * L2E),
                                              ex2f_(em_buf[u].y * L2E)));
    if (!isBwd) gpk_c[0] = ONEBF;                        // em_0 already folded into p0

    int tagA_nn = 0, tagB_nn = 0;
    int mskA_n, mskB_n, gate0_n, gate1_n;
    float emgA_n, emgB_n;

    for (int nb = 0; nb < 32; nb++) {
        const int k0 = nb * 16;

        // ---- prefetch: emissions/masks/gold-em for nb+1 (tags resolved), tags nb+2 ----
        if (nb < 31) {
            const int kn = k0 + 16;
            #pragma unroll
            for (int u = 0; u < 16; u++)
                em_buf[u] = __ldg((const float2*)(emL + (size_t)(gateBase + gdir*(kn + u)) * 16));
            mskA_n  = __ldg(mp + goldBase + kn + j8);
            mskB_n  = __ldg(mp + goldBase + kn + 8 + j8);
            gate0_n = __ldg(mp + gateBase + gdir*(kn + j8));
            gate1_n = __ldg(mp + gateBase + gdir*(kn + 8 + j8));
            emgA_n  = __ldg(emb + (size_t)(goldBase + kn + j8)*16     + tagA_n);
            emgB_n  = __ldg(emb + (size_t)(goldBase + kn + 8 + j8)*16 + tagB_n);
            if (nb < 30) {
                tagA_nn = __ldg(tp + goldBase + kn + 16 + j8);
                tagB_nn = __ldg(tp + goldBase + kn + 24 + j8);
            }
        }

        // ---- gold path: 2 timesteps per lane per block (all operands prefetched) ----
        {
            int t  = goldBase + k0 + j8;
            int tgp = __shfl_up_sync(FULL, tagA_c, 1, 8);
            int l7  = __shfl_sync(FULL, tagA_c, 7, 8);
            if (j8 == 0) tgp = carry_tag;
            carry_tag = l7;
            if (t == 0) {
                gold += s_start[tagA_c] + emgA_c;
                if (mskA_c) packlm = tagA_c;
            } else if (mskA_c) {
                gold += emgA_c + s_trans[tagA_c*16 + tgp];
                packlm = (t << 4) | tagA_c;
            }
            t   = goldBase + k0 + 8 + j8;
            tgp = __shfl_up_sync(FULL, tagB_c, 1, 8);
            l7  = __shfl_sync(FULL, tagB_c, 7, 8);
            if (j8 == 0) tgp = carry_tag;
            carry_tag = l7;
            if (mskB_c) {
                gold += emgB_c + s_trans[tagB_c*16 + tgp];
                packlm = (t << 4) | tagB_c;
            }
        }

        // ---- 16 recurrence steps (warp-uniform dispatch) ----
        const unsigned bal = __ballot_sync(FULL, (gate0_c != 0) && (gate1_c != 0));
        if (bal == FULL) {
            STEP_F(0);  STEP_F(1);  STEP_F(2);  STEP_F(3);
            STEP_F(4);  STEP_F(5);  STEP_FR(6); STEP_F(7);
            STEP_F(8);  STEP_F(9);  STEP_F(10); STEP_F(11);
            STEP_F(12); STEP_F(13); STEP_FR(14); STEP_F(15);
        } else {
            STEP_S(0,  gate0_c, 0); STEP_S(1,  gate0_c, 1);
            STEP_S(2,  gate0_c, 2); STEP_S(3,  gate0_c, 3);
            STEP_S(4,  gate0_c, 4); STEP_S(5,  gate0_c, 5);
            STEP_S(6,  gate0_c, 6); STEP_S(7,  gate0_c, 7);
            STEP_S(8,  gate1_c, 0); STEP_S(9,  gate1_c, 1);
            STEP_S(10, gate1_c, 2); STEP_S(11, gate1_c, 3);
            STEP_S(12, gate1_c, 4); STEP_S(13, gate1_c, 5);
            STEP_S(14, gate1_c, 6); STEP_S(15, gate1_c, 7);
        }

        // ---- convert prefetched block -> gpk; rotate pipeline ----
        if (nb < 31) {
            #pragma unroll
            for (int u = 0; u < 16; u++)
                gpk_c[u] = bf2u(__floats2bfloat162_rn(ex2f_(em_buf[u].x * L2E),
                                                      ex2f_(em_buf[u].y * L2E)));
            tagA_c = tagA_n; tagB_c = tagB_n;
            tagA_n = tagA_nn; tagB_n = tagB_nn;
            mskA_c = mskA_n; mskB_c = mskB_n;
            gate0_c = gate0_n; gate1_c = gate1_n;
            emgA_c = emgA_n; emgB_c = emgB_n;
        }
    }

    // ---- epilogue: Z = sum_s alpha_511(s) * beta_511(s) ----
    unsigned fin  = isBwd ? pku : ptrk;              // fwd: ptrk = alpha_511; bwd: pku = beta_511
    unsigned oth  = __shfl_sync(FULL, fin,  (lane + 8) & 31, 32);
    float    offO = __shfl_sync(FULL, off2, (lane + 8) & 31, 32);

    float z = 0.0f;
    if (!isBwd)
        z = bflo_f(fin)*bflo_f(oth) + bfhi_f(fin)*bfhi_f(oth);
    z += __shfl_xor_sync(FULL, z, 4, 8);
    z += __shfl_xor_sync(FULL, z, 2, 8);
    z += __shfl_xor_sync(FULL, z, 1, 8);

    gold += __shfl_xor_sync(FULL, gold, 4, 8);
    gold += __shfl_xor_sync(FULL, gold, 2, 8);
    gold += __shfl_xor_sync(FULL, gold, 1, 8);
    float goldO = __shfl_sync(FULL, gold, (lane + 8) & 31, 32);

    packlm = max(packlm, __shfl_xor_sync(FULL, packlm, 4, 8));
    packlm = max(packlm, __shfl_xor_sync(FULL, packlm, 2, 8));
    packlm = max(packlm, __shfl_xor_sync(FULL, packlm, 1, 8));
    int pmO = __shfl_sync(FULL, packlm, (lane + 8) & 31, 32);

    if ((lane & 15) == 0) {
        const int pm  = max(packlm, pmO);
        const int ltf = pm & 15;
        const float logZ = (off2 + offO + lg2f_(z)) * LN2;
        g_nll[b] = logZ - (gold + goldO + __ldg(end_t + ltf));
    }
}

__global__ void crf_reduce_kernel(float* __restrict__ out)
{
    __shared__ float sm[256];
    int tid = threadIdx.x;
    float v = g_nll[tid] + g_nll[tid + 256] + g_nll[tid + 512] + g_nll[tid + 768];
    sm[tid] = v;
    __syncthreads();
    #pragma unroll
    for (int s = 128; s > 0; s >>= 1) {
        if (tid < s) sm[tid] += sm[tid + s];
        __syncthreads();
    }
    if (tid == 0) out[0] = sm[0] * (1.0f / 1024.0f);
}

extern "C" void kernel_launch(void* const* d_in, const int* in_sizes, int n_in,
                              void* d_out, int out_size)
{
    const float* emissions = (const float*)d_in[0];
    const int*   tags      = (const int*)d_in[1];
    const int*   mask      = (const int*)d_in[2];
    const float* trans     = (const float*)d_in[3];
    const float* start_t   = (const float*)d_in[4];
    const float* end_t     = (const float*)d_in[5];
    float* out = (float*)d_out;

    crf_forward_kernel<<<128, 128>>>(emissions, tags, mask, trans, start_t, end_t);
    crf_reduce_kernel<<<1, 256>>>(out);
}